// round 9
// baseline (speedup 1.0000x reference)
#include <cuda_runtime.h>
#include <cuda_fp16.h>
#include <cstdint>

#define NV 10000
#define NC 100000
#define B  256
#define GPB 10                       // groups (of 8 clauses) per block
#define GRID_MAIN 1250               // 1250 * 10 * 8 = 100000, exact
#define GRID_PREP 2048
#define STAGES 2

// Dual table: row 2v = x, row 2v+1 = 1-x; each row 256 fp16 = 512 B.
// 10.24 MB, L2-resident. Both variants rounded directly from fp32 ->
// every literal value carries rel err <= 2^-11 regardless of negation.
__device__ __align__(16) __half2 g_tab[2 * NV * (B / 2)];
// Per literal: half2-offset of its table row: (2v+neg)*128. 1.2 MB.
__device__ __align__(16) unsigned int g_off[NC * 3];

// Fused prologue: detect index dtype, pack literal offsets, build fp16 dual
// table, init d_out. One kernel node.
__global__ void __launch_bounds__(256)
prep_k(const float* __restrict__ input,
       const unsigned int* __restrict__ idx_raw,
       const unsigned int* __restrict__ neg_raw,
       unsigned int* __restrict__ out) {
    __shared__ int s_is64;
    const int tid = threadIdx.x;

    // dtype probe: int64 data (small non-negative) -> odd 32-bit words all 0;
    // int32 data -> odd words are random indices, all-zero ~impossible.
    if (tid < 32) {
        unsigned int acc = 0;
        #pragma unroll
        for (int k = 0; k < 4; ++k) acc |= idx_raw[2 * (tid + 32 * k) + 1];
        acc = __reduce_or_sync(0xFFFFFFFFu, acc);
        if (tid == 0) s_is64 = (acc == 0) ? 1 : 0;
    }
    __syncthreads();
    const int stride = s_is64 ? 2 : 1;

    const int gtid = blockIdx.x * 256 + tid;
    const int gsz  = GRID_PREP * 256;

    if (gtid < B) out[gtid] = 0x7F800000u;   // +inf (d_out poisoned each replay)

    for (int i = gtid; i < NC * 3; i += gsz) {
        unsigned int v = idx_raw[i * stride];
        unsigned int n = neg_raw[i * stride] & 1u;
        if (v >= NV) v = NV - 1;              // defensive clamp: no OOB ever
        g_off[i] = v * 256u + n * 128u;
    }

    for (int i = gtid; i < NV * (B / 2); i += gsz) {
        int v = i >> 7;
        int j = i & 127;
        float2 x = ((const float2*)input)[i];
        g_tab[v * 256 + j]       = __floats2half2_rn(x.x, x.y);
        g_tab[v * 256 + 128 + j] = __floats2half2_rn(1.0f - x.x, 1.0f - x.y);
    }
}

__device__ __forceinline__ void cpa16(uint32_t dst, const void* src) {
    asm volatile("cp.async.cg.shared.global [%0], [%1], 16;" :: "r"(dst), "l"(src) : "memory");
}
__device__ __forceinline__ void cp_commit() {
    asm volatile("cp.async.commit_group;" ::: "memory");
}
__device__ __forceinline__ void cp_wait1() {
    asm volatile("cp.async.wait_group 1;" ::: "memory");
}

// cp.async-pipelined gather. 128 threads = 4 warps. Per group of 8 clauses:
// 24 literal rows (512 B each); warp w fetches rows {4k+w} with one 16B
// cp.async per lane -> 1 LDGSTS warp-instr per row. Index quads are fetched
// 2 groups ahead into a 4-slot SMEM ring inside the same commit groups.
__global__ void __launch_bounds__(128)
cnf_k(unsigned int* __restrict__ out) {
    __shared__ __align__(16) __half2 s_data[STAGES][24][128];   // 24 KB
    __shared__ __align__(16) unsigned int s_idx[4][24];         // 384 B

    const int t    = threadIdx.x;
    const int w    = t >> 5;
    const int lane = t & 31;
    const int base = blockIdx.x * GPB;
    const char* tab = (const char*)g_tab;

    // prologue: indices for groups 0,1 via direct loads
    if (t < 12) {
        int grp = t / 6, j = t % 6;
        uint4 v = __ldg((const uint4*)(g_off + (base + grp) * 24) + j);
        ((uint4*)s_idx[grp])[j] = v;
    }
    __syncthreads();

    auto issue_data = [&](int s, int slot) {
        #pragma unroll
        for (int k = 0; k < 6; ++k) {
            int lit = k * 4 + w;
            unsigned int off = s_idx[slot][lit];                    // warp-uniform LDS
            const char* src = tab + (size_t)off * 4 + lane * 16;
            uint32_t dst = (uint32_t)__cvta_generic_to_shared(&s_data[s][lit][lane * 4]);
            cpa16(dst, src);
        }
    };
    auto issue_idx = [&](int g, int slot) {
        if (t < 6) {
            const char* src = (const char*)(g_off + g * 24) + t * 16;
            uint32_t dst = (uint32_t)__cvta_generic_to_shared(&((uint4*)s_idx[slot])[t]);
            cpa16(dst, src);
        }
    };

    issue_data(0, 0);
    issue_idx(base + 2, 2);
    cp_commit();
    issue_data(1, 1);
    issue_idx(base + 3, 3);
    cp_commit();

    __half2 m = __halves2half2(__ushort_as_half(0x7C00), __ushort_as_half(0x7C00)); // +inf

    for (int i = 0; i < GPB; ++i) {
        cp_wait1();            // group i's commit arrived (all but newest done)
        __syncthreads();       // publish async arrivals across warps
        const int s = i & 1;

        __half2 c0 = __hmax2(__hmax2(s_data[s][0][t],  s_data[s][1][t]),  s_data[s][2][t]);
        __half2 c1 = __hmax2(__hmax2(s_data[s][3][t],  s_data[s][4][t]),  s_data[s][5][t]);
        __half2 c2 = __hmax2(__hmax2(s_data[s][6][t],  s_data[s][7][t]),  s_data[s][8][t]);
        __half2 c3 = __hmax2(__hmax2(s_data[s][9][t],  s_data[s][10][t]), s_data[s][11][t]);
        __half2 c4 = __hmax2(__hmax2(s_data[s][12][t], s_data[s][13][t]), s_data[s][14][t]);
        __half2 c5 = __hmax2(__hmax2(s_data[s][15][t], s_data[s][16][t]), s_data[s][17][t]);
        __half2 c6 = __hmax2(__hmax2(s_data[s][18][t], s_data[s][19][t]), s_data[s][20][t]);
        __half2 c7 = __hmax2(__hmax2(s_data[s][21][t], s_data[s][22][t]), s_data[s][23][t]);
        __half2 l0 = __hmin2(__hmin2(c0, c1), __hmin2(c2, c3));
        __half2 l1 = __hmin2(__hmin2(c4, c5), __hmin2(c6, c7));
        m = __hmin2(m, __hmin2(l0, l1));

        __syncthreads();       // all reads done before refilling this stage
        if (i + 2 < GPB) {
            issue_data(s, (i + 2) & 3);
            if (i + 4 < GPB) issue_idx(base + i + 4, (i + 4) & 3);
        }
        cp_commit();           // empty commits on tail keep wait-count aligned
    }

    // uint bit order == float order for non-negative floats
    atomicMin(&out[2 * t + 0], __float_as_uint(__low2float(m)));
    atomicMin(&out[2 * t + 1], __float_as_uint(__high2float(m)));
}

extern "C" void kernel_launch(void* const* d_in, const int* in_sizes, int n_in,
                              void* d_out, int out_size) {
    const float*        input   = (const float*)d_in[0];
    const unsigned int* idx_raw = (const unsigned int*)d_in[1];
    const unsigned int* neg_raw = (const unsigned int*)d_in[2];
    unsigned int*       out     = (unsigned int*)d_out;

    prep_k<<<GRID_PREP, 256>>>(input, idx_raw, neg_raw, out);
    cnf_k<<<GRID_MAIN, 128>>>(out);
}

// round 11
// speedup vs baseline: 1.0746x; 1.0746x over previous
#include <cuda_runtime.h>
#include <cuda_fp16.h>
#include <cstdint>

#define NV 10000
#define NC 100000
#define B  256
#define NPAIRS (NC / 2)              // 50000 clause-pairs
#define GRID_MAIN 1184               // 148 SMs * 8 blocks
#define NWARPS (GRID_MAIN * 4)       // 4736 warp processors
#define GRID_PREP 2048

// Dual table: row 2v = x, row 2v+1 = 1-x; each row 128 half2 = 512 B.
// 10.24 MB, L2-resident. Both variants rounded directly from fp32 ->
// every literal value carries rel err <= 2^-11 regardless of negation.
__device__ __align__(16) __half2 g_tab[2 * NV * (B / 2)];
// Per literal: half2-offset of its table row: (2v+neg)*128. 1.2 MB.
__device__ __align__(16) unsigned int g_off[NC * 3];

// Fused prologue: detect index dtype, pack literal offsets, build fp16 dual
// table, init d_out. One kernel node.
__global__ void __launch_bounds__(256)
prep_k(const float* __restrict__ input,
       const unsigned int* __restrict__ idx_raw,
       const unsigned int* __restrict__ neg_raw,
       unsigned int* __restrict__ out) {
    __shared__ int s_is64;
    const int tid = threadIdx.x;

    // dtype probe: int64 data (small non-negative) -> odd 32-bit words all 0;
    // int32 data -> odd words are random indices, all-zero ~impossible.
    if (tid < 32) {
        unsigned int acc = 0;
        #pragma unroll
        for (int k = 0; k < 4; ++k) acc |= idx_raw[2 * (tid + 32 * k) + 1];
        acc = __reduce_or_sync(0xFFFFFFFFu, acc);
        if (tid == 0) s_is64 = (acc == 0) ? 1 : 0;
    }
    __syncthreads();
    const int stride = s_is64 ? 2 : 1;

    const int gtid = blockIdx.x * 256 + tid;
    const int gsz  = GRID_PREP * 256;

    if (gtid < B) out[gtid] = 0x7F800000u;   // +inf (d_out poisoned each replay)

    for (int i = gtid; i < NC * 3; i += gsz) {
        unsigned int v = idx_raw[i * stride];
        unsigned int n = neg_raw[i * stride] & 1u;
        if (v >= NV) v = NV - 1;              // defensive clamp: no OOB ever
        g_off[i] = v * 256u + n * 128u;
    }

    for (int i = gtid; i < NV * (B / 2); i += gsz) {
        int v = i >> 7;
        int j = i & 127;
        float2 x = ((const float2*)input)[i];
        g_tab[v * 256 + j]       = __floats2half2_rn(x.x, x.y);
        g_tab[v * 256 + 128 + j] = __floats2half2_rn(1.0f - x.x, 1.0f - x.y);
    }
}

__device__ __forceinline__ __half2 h2(unsigned int u) {
    return *reinterpret_cast<__half2*>(&u);
}

// Warp-per-clause gather: one LDG.128 warp-instruction fetches one whole
// 512 B literal row (lane l takes half2s [4l,4l+4) = batch elems [8l,8l+8)).
// All three literals of a clause land in the SAME lanes -> clause max is
// in-lane, no shuffles. 2 clauses per iteration = 6 LDG.128 in flight
// (24 data regs, the footprint proven to batch at the 64-reg budget).
// Next pair's indices prefetched during data flight.
__global__ void __launch_bounds__(128, 8)
cnf_k(unsigned int* __restrict__ out) {
    __shared__ uint4 s_m[4][32];     // per-warp partial mins, 2 KB

    const int t    = threadIdx.x;
    const int w    = t >> 5;
    const int lane = t & 31;
    const int gw   = blockIdx.x * 4 + w;

    const __half2 inf2 = __halves2half2(__ushort_as_half(0x7C00), __ushort_as_half(0x7C00));
    __half2 m0 = inf2, m1 = inf2, m2 = inf2, m3 = inf2;

    // pair p -> 6 literal offsets at g_off + p*6 (24 B, 8 B aligned)
    int p = gw;
    uint2 ia, ib, ic;
    if (p < NPAIRS) {
        const uint2* q = (const uint2*)(g_off + p * 6);
        ia = __ldg(&q[0]); ib = __ldg(&q[1]); ic = __ldg(&q[2]);
    }
    while (p < NPAIRS) {
        // 6 row gathers: one LDG.128 each (lane-sliced full row)
        uint4 xA0 = __ldg((const uint4*)(g_tab + ia.x) + lane);
        uint4 xA1 = __ldg((const uint4*)(g_tab + ia.y) + lane);
        uint4 xA2 = __ldg((const uint4*)(g_tab + ib.x) + lane);
        uint4 xB0 = __ldg((const uint4*)(g_tab + ib.y) + lane);
        uint4 xB1 = __ldg((const uint4*)(g_tab + ic.x) + lane);
        uint4 xB2 = __ldg((const uint4*)(g_tab + ic.y) + lane);

        // prefetch next pair's indices while the 6 gathers are in flight
        int pn = p + NWARPS;
        if (pn < NPAIRS) {
            const uint2* qn = (const uint2*)(g_off + pn * 6);
            ia = __ldg(&qn[0]); ib = __ldg(&qn[1]); ic = __ldg(&qn[2]);
        }
        p = pn;

        __half2 cA0 = __hmax2(__hmax2(h2(xA0.x), h2(xA1.x)), h2(xA2.x));
        __half2 cA1 = __hmax2(__hmax2(h2(xA0.y), h2(xA1.y)), h2(xA2.y));
        __half2 cA2 = __hmax2(__hmax2(h2(xA0.z), h2(xA1.z)), h2(xA2.z));
        __half2 cA3 = __hmax2(__hmax2(h2(xA0.w), h2(xA1.w)), h2(xA2.w));
        __half2 cB0 = __hmax2(__hmax2(h2(xB0.x), h2(xB1.x)), h2(xB2.x));
        __half2 cB1 = __hmax2(__hmax2(h2(xB0.y), h2(xB1.y)), h2(xB2.y));
        __half2 cB2 = __hmax2(__hmax2(h2(xB0.z), h2(xB1.z)), h2(xB2.z));
        __half2 cB3 = __hmax2(__hmax2(h2(xB0.w), h2(xB1.w)), h2(xB2.w));

        m0 = __hmin2(m0, __hmin2(cA0, cB0));
        m1 = __hmin2(m1, __hmin2(cA1, cB1));
        m2 = __hmin2(m2, __hmin2(cA2, cB2));
        m3 = __hmin2(m3, __hmin2(cA3, cB3));
    }

    // block reduce: 4 warps hold full-batch partials over the same lanes
    uint4 mv;
    mv.x = *reinterpret_cast<unsigned int*>(&m0);
    mv.y = *reinterpret_cast<unsigned int*>(&m1);
    mv.z = *reinterpret_cast<unsigned int*>(&m2);
    mv.w = *reinterpret_cast<unsigned int*>(&m3);
    s_m[w][lane] = mv;
    __syncthreads();

    // thread t -> half2 column j = t (lane = t>>2, comp = t&3): conflict-free
    {
        int l = t >> 2, i = t & 3;
        const unsigned int* c0 = (const unsigned int*)&s_m[0][l];
        const unsigned int* c1 = (const unsigned int*)&s_m[1][l];
        const unsigned int* c2 = (const unsigned int*)&s_m[2][l];
        const unsigned int* c3 = (const unsigned int*)&s_m[3][l];
        __half2 r = __hmin2(__hmin2(h2(c0[i]), h2(c1[i])), __hmin2(h2(c2[i]), h2(c3[i])));
        // uint bit order == float order for non-negative floats
        atomicMin(&out[2 * t + 0], __float_as_uint(__low2float(r)));
        atomicMin(&out[2 * t + 1], __float_as_uint(__high2float(r)));
    }
}

extern "C" void kernel_launch(void* const* d_in, const int* in_sizes, int n_in,
                              void* d_out, int out_size) {
    const float*        input   = (const float*)d_in[0];
    const unsigned int* idx_raw = (const unsigned int*)d_in[1];
    const unsigned int* neg_raw = (const unsigned int*)d_in[2];
    unsigned int*       out     = (unsigned int*)d_out;

    prep_k<<<GRID_PREP, 256>>>(input, idx_raw, neg_raw, out);
    cnf_k<<<GRID_MAIN, 128>>>(out);
}